// round 3
// baseline (speedup 1.0000x reference)
#include <cuda_runtime.h>

#define NB   32
#define DD   256
#define MMs  784
#define CINc 2048
#define MAT  (DD*DD)          // 65536
#define BMAT (NB*MAT)         // 2,097,152
#define KC   8                // K chunk

typedef unsigned long long ull;

// Scratch (device globals; no allocation anywhere)
__device__ float g_y[NB*DD*MMs];      // BN'd ReLU'd activations [b][d][m]
__device__ float g_mats[9u*BMAT];     // 9 batched 256x256 buffers
__device__ float g_small[16384];      // bn stats, rowmean, tr

// ---------------------------------------------------------------------------
__device__ __forceinline__ float warpReduce(float v) {
    #pragma unroll
    for (int o = 16; o; o >>= 1) v += __shfl_down_sync(0xffffffffu, v, o);
    return v;
}

__device__ __forceinline__ ull dup2(float v) {
    unsigned u = __float_as_uint(v);
    ull r;
    asm("mov.b64 %0, {%1, %1};" : "=l"(r) : "r"(u));
    return r;
}
__device__ __forceinline__ void unpack2(ull p, float& lo, float& hi) {
    unsigned a, b;
    asm("mov.b64 {%0, %1}, %2;" : "=r"(a), "=r"(b) : "l"(p));
    lo = __uint_as_float(a); hi = __uint_as_float(b);
}
#define FFMA2(d, a, b) asm("fma.rn.f32x2 %0, %1, %2, %0;" : "+l"(d) : "l"(a), "l"(b))

// sym 128-tile map: t -> (ti,tj) in {(0,0),(0,1),(1,1)}
__device__ __forceinline__ void tilemap2(int t, int& ti, int& tj) {
    ti = (t == 2) ? 1 : 0;
    tj = (t == 0) ? 0 : 1;
}

// ===========================================================================
// Core compute: 128x128 tile, 256 threads, 8x8 per thread (4 packed col-pairs)
// As2: A pre-duplicated {v,v} per element, [KC][132] ull, indexed [k][row]
// Bs : plain floats [KC][132], indexed [k][col]
// ===========================================================================
#define GEMM_COMPUTE2(AsB, BsB)                                                \
    {                                                                          \
        _Pragma("unroll")                                                      \
        for (int kk = 0; kk < KC; kk++) {                                      \
            ulonglong2 a01 = *(const ulonglong2*)&AsB[kk][tr8 * 8 + 0];        \
            ulonglong2 a23 = *(const ulonglong2*)&AsB[kk][tr8 * 8 + 2];        \
            ulonglong2 a45 = *(const ulonglong2*)&AsB[kk][tr8 * 8 + 4];        \
            ulonglong2 a67 = *(const ulonglong2*)&AsB[kk][tr8 * 8 + 6];        \
            ulonglong2 bq0 = *(const ulonglong2*)&BsB[kk][tc * 8 + 0];         \
            ulonglong2 bq1 = *(const ulonglong2*)&BsB[kk][tc * 8 + 4];         \
            ull ar[8] = {a01.x, a01.y, a23.x, a23.y, a45.x, a45.y, a67.x, a67.y};\
            ull br[4] = {bq0.x, bq0.y, bq1.x, bq1.y};                          \
            _Pragma("unroll")                                                  \
            for (int i = 0; i < 8; i++)                                        \
                _Pragma("unroll")                                              \
                for (int j = 0; j < 4; j++)                                    \
                    FFMA2(acc2[i][j], ar[i], br[j]);                           \
        }                                                                      \
    }

// ---------------------------------------------------------------------------
// conv 1x1 GEMM: y[b][d][m] = sum_c w[d][c] * x[b][c][m]
// grid (7, 2, NB), 256 threads.  Last n-tile partial (784 = 6*128 + 16).
// ---------------------------------------------------------------------------
__global__ __launch_bounds__(256, 1) void conv_gemm(
    const float* __restrict__ x, const float* __restrict__ w, float* __restrict__ y)
{
    const int b  = blockIdx.z;
    const int m0 = blockIdx.y * 128;
    const int n0 = blockIdx.x * 128;
    const float* Ap = w;
    const float* Bp = x + (size_t)b * CINc * MMs;
    float* Dp = y + (size_t)b * DD * MMs;

    __shared__ __align__(16) ull   As2[2][KC][132];
    __shared__ __align__(16) float Bs [2][KC][132];
    const int tid = threadIdx.x;
    const int tc = tid & 15, tr8 = tid >> 4;
    const int arow = tid >> 1, aq = tid & 1;        // A: row 0..127, k-quad 0..1
    const int bkr  = tid >> 5, bnc = tid & 31;      // B: k-row 0..7, col-quad 0..31

    float4 pa, pb;
    ull acc2[8][4] = {};

    // prologue chunk 0
    pa = *(const float4*)(Ap + (size_t)(m0 + arow) * CINc + aq * 4);
    {
        const int col = n0 + bnc * 4;
        pb = (col < MMs) ? *(const float4*)(Bp + (size_t)bkr * MMs + col)
                         : make_float4(0.f, 0.f, 0.f, 0.f);
    }
    As2[0][aq*4+0][arow] = dup2(pa.x); As2[0][aq*4+1][arow] = dup2(pa.y);
    As2[0][aq*4+2][arow] = dup2(pa.z); As2[0][aq*4+3][arow] = dup2(pa.w);
    *(float4*)&Bs[0][bkr][bnc*4] = pb;
    __syncthreads();

    const int NCH = CINc / KC;   // 256
    for (int ch = 0; ch < NCH; ch++) {
        const int buf = ch & 1;
        if (ch + 1 < NCH) {
            const int k0 = (ch + 1) * KC;
            pa = *(const float4*)(Ap + (size_t)(m0 + arow) * CINc + k0 + aq * 4);
            const int col = n0 + bnc * 4;
            pb = (col < MMs) ? *(const float4*)(Bp + (size_t)(k0 + bkr) * MMs + col)
                             : make_float4(0.f, 0.f, 0.f, 0.f);
        }
        GEMM_COMPUTE2(As2[buf], Bs[buf]);
        if (ch + 1 < NCH) {
            const int nb = buf ^ 1;
            As2[nb][aq*4+0][arow] = dup2(pa.x); As2[nb][aq*4+1][arow] = dup2(pa.y);
            As2[nb][aq*4+2][arow] = dup2(pa.z); As2[nb][aq*4+3][arow] = dup2(pa.w);
            *(float4*)&Bs[nb][bkr][bnc*4] = pb;
            __syncthreads();
        }
    }

    #pragma unroll
    for (int i = 0; i < 8; i++) {
        const int r = m0 + tr8 * 8 + i;
        float v[8];
        #pragma unroll
        for (int j = 0; j < 4; j++) unpack2(acc2[i][j], v[2*j], v[2*j+1]);
        const int c = n0 + tc * 8;
        if (c + 7 < MMs) {
            *(float4*)(Dp + (size_t)r * MMs + c)     = make_float4(v[0], v[1], v[2], v[3]);
            *(float4*)(Dp + (size_t)r * MMs + c + 4) = make_float4(v[4], v[5], v[6], v[7]);
        } else {
            #pragma unroll
            for (int j = 0; j < 8; j++)
                if (c + j < MMs) Dp[(size_t)r * MMs + c + j] = v[j];
        }
    }
}

// ---------------------------------------------------------------------------
// BN stats over (b, m) per channel d
// ---------------------------------------------------------------------------
__global__ void bn_stats(const float* __restrict__ y, float* __restrict__ mean,
                         float* __restrict__ rstd)
{
    const int d = blockIdx.x;
    const int t = threadIdx.x;
    float s = 0.f, s2 = 0.f;
    for (int b = 0; b < NB; b++) {
        const float* p = y + (size_t)b * DD * MMs + (size_t)d * MMs;
        for (int m = t; m < MMs; m += 256) { float v = p[m]; s += v; s2 = fmaf(v, v, s2); }
    }
    __shared__ float sh1[8], sh2[8];
    const int lane = t & 31, wid = t >> 5;
    s = warpReduce(s); s2 = warpReduce(s2);
    if (lane == 0) { sh1[wid] = s; sh2[wid] = s2; }
    __syncthreads();
    if (wid == 0) {
        s  = (lane < 8) ? sh1[lane] : 0.f;
        s2 = (lane < 8) ? sh2[lane] : 0.f;
        s = warpReduce(s); s2 = warpReduce(s2);
        if (lane == 0) {
            const float N = (float)(NB * MMs);
            float mu  = s / N;
            float var = s2 / N - mu * mu;
            mean[d] = mu;
            rstd[d] = rsqrtf(var + 1e-5f);
        }
    }
}

// ---------------------------------------------------------------------------
// BN apply + ReLU (in place) + per-(b,d) row mean
// ---------------------------------------------------------------------------
__global__ void bn_apply(float* __restrict__ y, const float* __restrict__ mean,
                         const float* __restrict__ rstd, const float* __restrict__ gamma,
                         const float* __restrict__ beta, float* __restrict__ rowmean)
{
    const int bd = blockIdx.x;
    const int d  = bd & (DD - 1);
    float* p = y + (size_t)bd * MMs;
    const float mu = mean[d], rs = rstd[d], g = gamma[d], be = beta[d];
    const int t = threadIdx.x;
    float s = 0.f;
    for (int m = t; m < MMs; m += 256) {
        float v = fmaf((p[m] - mu) * rs, g, be);
        v = fmaxf(v, 0.f);
        p[m] = v;
        s += v;
    }
    __shared__ float sh[8];
    const int lane = t & 31, wid = t >> 5;
    s = warpReduce(s);
    if (lane == 0) sh[wid] = s;
    __syncthreads();
    if (wid == 0) {
        s = (lane < 8) ? sh[lane] : 0.f;
        s = warpReduce(s);
        if (lane == 0) rowmean[bd] = s * (1.0f / MMs);
    }
}

// ---------------------------------------------------------------------------
// Covariance (symmetric, 3 tiles of 128x128, exact mirror):
// C[b] = (Y Y^T)/784 - mu mu^T.   grid (3, 1, NB), 256 threads
// ---------------------------------------------------------------------------
__global__ __launch_bounds__(256, 1) void cov_sym(
    const float* __restrict__ y, const float* __restrict__ rowmean, float* __restrict__ C)
{
    const int b = blockIdx.z;
    int ti, tj; tilemap2(blockIdx.x, ti, tj);
    const int i0 = ti * 128, j0 = tj * 128;
    const float* Yb = y + (size_t)b * DD * MMs;

    __shared__ __align__(16) ull   As2[2][KC][132];
    __shared__ __align__(16) float Bs [2][KC][132];
    const int tid = threadIdx.x;
    const int tc = tid & 15, tr8 = tid >> 4;
    const int arow = tid >> 1, aq = tid & 1;

    float4 pa, pb;
    ull acc2[8][4] = {};

    pa = *(const float4*)(Yb + (size_t)(i0 + arow) * MMs + aq * 4);
    pb = *(const float4*)(Yb + (size_t)(j0 + arow) * MMs + aq * 4);
    As2[0][aq*4+0][arow] = dup2(pa.x); As2[0][aq*4+1][arow] = dup2(pa.y);
    As2[0][aq*4+2][arow] = dup2(pa.z); As2[0][aq*4+3][arow] = dup2(pa.w);
    Bs[0][aq*4+0][arow] = pb.x; Bs[0][aq*4+1][arow] = pb.y;
    Bs[0][aq*4+2][arow] = pb.z; Bs[0][aq*4+3][arow] = pb.w;
    __syncthreads();

    const int NCH = MMs / KC;   // 98
    for (int ch = 0; ch < NCH; ch++) {
        const int buf = ch & 1;
        if (ch + 1 < NCH) {
            const int k0 = (ch + 1) * KC;
            pa = *(const float4*)(Yb + (size_t)(i0 + arow) * MMs + k0 + aq * 4);
            pb = *(const float4*)(Yb + (size_t)(j0 + arow) * MMs + k0 + aq * 4);
        }
        GEMM_COMPUTE2(As2[buf], Bs[buf]);
        if (ch + 1 < NCH) {
            const int nb = buf ^ 1;
            As2[nb][aq*4+0][arow] = dup2(pa.x); As2[nb][aq*4+1][arow] = dup2(pa.y);
            As2[nb][aq*4+2][arow] = dup2(pa.z); As2[nb][aq*4+3][arow] = dup2(pa.w);
            Bs[nb][aq*4+0][arow] = pb.x; Bs[nb][aq*4+1][arow] = pb.y;
            Bs[nb][aq*4+2][arow] = pb.z; Bs[nb][aq*4+3][arow] = pb.w;
            __syncthreads();
        }
    }

    const float invM = 1.0f / (float)MMs;
    const float* mu = rowmean + b * DD;
    float* Cb = C + (size_t)b * MAT;
    #pragma unroll
    for (int i = 0; i < 8; i++) {
        const int r = i0 + tr8 * 8 + i;
        const float mi = mu[r];
        const int c0 = j0 + tc * 8;
        float v[8];
        #pragma unroll
        for (int j = 0; j < 4; j++) unpack2(acc2[i][j], v[2*j], v[2*j+1]);
        #pragma unroll
        for (int j = 0; j < 8; j++) v[j] = v[j] * invM - mi * mu[c0 + j];
        *(float4*)(Cb + (size_t)r * DD + c0)     = make_float4(v[0], v[1], v[2], v[3]);
        *(float4*)(Cb + (size_t)r * DD + c0 + 4) = make_float4(v[4], v[5], v[6], v[7]);
        if (ti != tj) {
            #pragma unroll
            for (int j = 0; j < 8; j++) Cb[(size_t)(c0+j) * DD + r] = v[j];
        }
    }
}

// ---------------------------------------------------------------------------
// Batched symmetric-output 256^3 GEMM, 3 tiles of 128x128, mirrored.
// epi 0: D = P;  1: D = 1.5I - 0.5P;  2: D = P*rsqrt(tr);
// 3: fused SICE: L = sice(L, Cn - P, dec)     grid (3, 1, NB), 256 threads
// ---------------------------------------------------------------------------
__device__ __forceinline__ float sice_f(float L, float g12, float dec)
{
    float lp = fmaxf(L, 0.f);
    float lm = fmaxf(-L, 0.f);
    lp = fmaxf(lp - dec * (g12 + 0.07f), 0.f);
    lm = fmaxf(lm - dec * (-g12 + 0.07f), 0.f);
    return lp - lm;
}

#define GEMM256_LOAD(dst_buf, k0)                                              \
    {                                                                          \
        pa = *(const float4*)(Ap + (size_t)(m0 + arow) * DD + (k0) + aq * 4);  \
        pb = *(const float4*)(Bp + (size_t)((k0) + bkr) * DD + n0 + bnc * 4);  \
    }
#define GEMM256_STORE(nb)                                                      \
    {                                                                          \
        As2[nb][aq*4+0][arow] = dup2(pa.x); As2[nb][aq*4+1][arow] = dup2(pa.y);\
        As2[nb][aq*4+2][arow] = dup2(pa.z); As2[nb][aq*4+3][arow] = dup2(pa.w);\
        *(float4*)&Bs[nb][bkr][bnc*4] = pb;                                    \
    }

__global__ __launch_bounds__(256, 1) void bgemm_sym(
    const float* __restrict__ Ab, const float* __restrict__ Bb, float* __restrict__ Db,
    const float* __restrict__ tr, int epi, const float* __restrict__ Cn, float dec)
{
    const int b = blockIdx.z;
    int ti, tj; tilemap2(blockIdx.x, ti, tj);
    const int m0 = ti * 128, n0 = tj * 128;
    const float* Ap = Ab + (size_t)b * MAT;
    const float* Bp = Bb + (size_t)b * MAT;
    float* Dp = Db + (size_t)b * MAT;

    __shared__ __align__(16) ull   As2[2][KC][132];
    __shared__ __align__(16) float Bs [2][KC][132];
    const int tid = threadIdx.x;
    const int tc = tid & 15, tr8 = tid >> 4;
    const int arow = tid >> 1, aq = tid & 1;
    const int bkr  = tid >> 5, bnc = tid & 31;

    float4 pa, pb;
    ull acc2[8][4] = {};

    GEMM256_LOAD(0, 0);
    GEMM256_STORE(0);
    __syncthreads();

    const int NCH = DD / KC;   // 32
    for (int ch = 0; ch < NCH; ch++) {
        const int buf = ch & 1;
        if (ch + 1 < NCH) GEMM256_LOAD(buf, (ch + 1) * KC);
        GEMM_COMPUTE2(As2[buf], Bs[buf]);
        if (ch + 1 < NCH) {
            const int nb = buf ^ 1;
            GEMM256_STORE(nb);
            __syncthreads();
        }
    }

    const float rs = (epi == 2) ? rsqrtf(tr[b]) : 1.0f;
    const float* Cb = (epi == 3) ? (Cn + (size_t)b * MAT) : nullptr;
    #pragma unroll
    for (int i = 0; i < 8; i++) {
        const int r = m0 + tr8 * 8 + i;
        const int c0 = n0 + tc * 8;
        float v[8];
        #pragma unroll
        for (int j = 0; j < 4; j++) unpack2(acc2[i][j], v[2*j], v[2*j+1]);
        if (epi == 1) {
            #pragma unroll
            for (int j = 0; j < 8; j++)
                v[j] = ((r == c0 + j) ? 1.5f : 0.0f) - 0.5f * v[j];
        } else if (epi == 2) {
            #pragma unroll
            for (int j = 0; j < 8; j++) v[j] *= rs;
        } else if (epi == 3) {
            #pragma unroll
            for (int j = 0; j < 8; j++) {
                float Lv = Dp[(size_t)r * DD + c0 + j];
                float g  = Cb[(size_t)r * DD + c0 + j] - v[j];
                v[j] = sice_f(Lv, g, dec);
            }
        }
        *(float4*)(Dp + (size_t)r * DD + c0)     = make_float4(v[0], v[1], v[2], v[3]);
        *(float4*)(Dp + (size_t)r * DD + c0 + 4) = make_float4(v[4], v[5], v[6], v[7]);
        if (ti != tj) {
            #pragma unroll
            for (int j = 0; j < 8; j++) Dp[(size_t)(c0+j) * DD + r] = v[j];
        }
    }
}

// ---------------------------------------------------------------------------
// Fused pair: z<NB -> D1 = A1@B1 ; z>=NB -> D2 = A2@B2 (symmetric, epi 0)
// grid (3, 1, 2*NB), 256 threads
// ---------------------------------------------------------------------------
__global__ __launch_bounds__(256, 1) void bgemm_pair(
    const float* __restrict__ A1, const float* __restrict__ B1, float* __restrict__ D1,
    const float* __restrict__ A2, const float* __restrict__ B2, float* __restrict__ D2)
{
    const int z = blockIdx.z;
    const int b = z & (NB - 1);
    const bool second = z >= NB;
    const float* Ap = (second ? A2 : A1) + (size_t)b * MAT;
    const float* Bp = (second ? B2 : B1) + (size_t)b * MAT;
    float* Dp = (second ? D2 : D1) + (size_t)b * MAT;

    int ti, tj; tilemap2(blockIdx.x, ti, tj);
    const int m0 = ti * 128, n0 = tj * 128;

    __shared__ __align__(16) ull   As2[2][KC][132];
    __shared__ __align__(16) float Bs [2][KC][132];
    const int tid = threadIdx.x;
    const int tc = tid & 15, tr8 = tid >> 4;
    const int arow = tid >> 1, aq = tid & 1;
    const int bkr  = tid >> 5, bnc = tid & 31;

    float4 pa, pb;
    ull acc2[8][4] = {};

    GEMM256_LOAD(0, 0);
    GEMM256_STORE(0);
    __syncthreads();

    const int NCH = DD / KC;
    for (int ch = 0; ch < NCH; ch++) {
        const int buf = ch & 1;
        if (ch + 1 < NCH) GEMM256_LOAD(buf, (ch + 1) * KC);
        GEMM_COMPUTE2(As2[buf], Bs[buf]);
        if (ch + 1 < NCH) {
            const int nb = buf ^ 1;
            GEMM256_STORE(nb);
            __syncthreads();
        }
    }

    #pragma unroll
    for (int i = 0; i < 8; i++) {
        const int r = m0 + tr8 * 8 + i;
        const int c0 = n0 + tc * 8;
        float v[8];
        #pragma unroll
        for (int j = 0; j < 4; j++) unpack2(acc2[i][j], v[2*j], v[2*j+1]);
        *(float4*)(Dp + (size_t)r * DD + c0)     = make_float4(v[0], v[1], v[2], v[3]);
        *(float4*)(Dp + (size_t)r * DD + c0 + 4) = make_float4(v[4], v[5], v[6], v[7]);
        if (ti != tj) {
            #pragma unroll
            for (int j = 0; j < 8; j++) Dp[(size_t)(c0+j) * DD + r] = v[j];
        }
    }
}

// ---------------------------------------------------------------------------
// small kernels
// ---------------------------------------------------------------------------
__global__ void tracek(const float* __restrict__ X, float* __restrict__ tr)
{
    const int b = blockIdx.x;
    const int t = threadIdx.x;
    float v = X[(size_t)b * MAT + t * 257];
    __shared__ float sh[8];
    const int lane = t & 31, wid = t >> 5;
    v = warpReduce(v);
    if (lane == 0) sh[wid] = v;
    __syncthreads();
    if (wid == 0) {
        v = (lane < 8) ? sh[lane] : 0.f;
        v = warpReduce(v);
        if (lane == 0) tr[b] = v;
    }
}

__global__ void tracek_j(const float* __restrict__ X, const float* __restrict__ jitter,
                         float* __restrict__ tr)
{
    const int b = blockIdx.x;
    const int t = threadIdx.x;
    float v = X[(size_t)b * MAT + t * 257] + 1e-10f + 1e-9f * jitter[t];
    __shared__ float sh[8];
    const int lane = t & 31, wid = t >> 5;
    v = warpReduce(v);
    if (lane == 0) sh[wid] = v;
    __syncthreads();
    if (wid == 0) {
        v = (lane < 8) ? sh[lane] : 0.f;
        v = warpReduce(v);
        if (lane == 0) tr[b] = v;
    }
}

__global__ void scalek(float* __restrict__ C, const float* __restrict__ tr)
{
    const int idx = blockIdx.x * 256 + threadIdx.x;
    C[idx] *= (1.0f / tr[idx >> 16]);
}

// A = (S + Ij)/tr[b];  ZY0 = 0.5*(3I - A)
__global__ void prep_ns(const float* __restrict__ S, const float* __restrict__ jitter,
                        const float* __restrict__ tr, float* __restrict__ A,
                        float* __restrict__ ZY)
{
    const int idx = blockIdx.x * 256 + threadIdx.x;
    const int b = idx >> 16, rc = idx & 65535, r = rc >> 8, c = rc & 255;
    float v = S[idx];
    if (r == c) v += 1e-10f + 1e-9f * jitter[r];
    float a = v * (1.0f / tr[b]);
    A[idx] = a;
    ZY[idx] = (r == c ? 1.5f : 0.0f) - 0.5f * a;
}

__global__ void gather_out(const float* __restrict__ L, const float* __restrict__ tr,
                           float* __restrict__ out)
{
    const int b = blockIdx.y, i = blockIdx.x, j = threadIdx.x;
    if (j < i) return;
    const float s = rsqrtf(tr[b]);
    const int k = i * 256 - (i * (i - 1)) / 2 + (j - i);
    out[(size_t)b * 32896 + k] = L[(size_t)b * MAT + i * 256 + j] * s;
}

// ---------------------------------------------------------------------------
// Host orchestration
// ---------------------------------------------------------------------------
static void run_inv(const float* S, const float* jitter, float* zz, float* tr,
                    float* A, float* Y, float* Z, float* Y2, float* Z2, float* ZYt)
{
    const dim3 gs(3, 1, NB);
    tracek_j<<<NB, 256>>>(S, jitter, tr);
    prep_ns<<<BMAT / 256, 256>>>(S, jitter, tr, A, Z);    // Z = ZY0
    bgemm_sym<<<gs, 256>>>(A, Z, Y, tr, 0, nullptr, 0.f); // Y = A @ ZY0
    float *Yc = Y, *Zc = Z, *Ya = Y2, *Za = Z2;
    for (int it = 0; it < 5; it++) {
        bgemm_sym<<<gs, 256>>>(Zc, Yc, ZYt, tr, 1, nullptr, 0.f);   // ZY = 1.5I-0.5 Z@Y
        bgemm_pair<<<dim3(3, 1, 2 * NB), 256>>>(Yc, ZYt, Ya, ZYt, Zc, Za);
        float* t1 = Yc; Yc = Ya; Ya = t1;
        float* t2 = Zc; Zc = Za; Za = t2;
    }
    bgemm_sym<<<gs, 256>>>(Zc, Yc, ZYt, tr, 1, nullptr, 0.f);
    bgemm_sym<<<gs, 256>>>(ZYt, Zc, zz, tr, 2, nullptr, 0.f);       // * tr^-0.5
}

extern "C" void kernel_launch(void* const* d_in, const int* in_sizes, int n_in,
                              void* d_out, int out_size)
{
    (void)in_sizes; (void)n_in; (void)out_size;
    const float* x      = (const float*)d_in[0];
    const float* w      = (const float*)d_in[1];
    const float* gamma  = (const float*)d_in[2];
    const float* beta   = (const float*)d_in[3];
    const float* jitter = (const float*)d_in[4];
    float* out = (float*)d_out;

    float *y, *mats, *small;
    cudaGetSymbolAddress((void**)&y, g_y);
    cudaGetSymbolAddress((void**)&mats, g_mats);
    cudaGetSymbolAddress((void**)&small, g_small);

    float* Cn  = mats + 0u * BMAT;
    float* A   = mats + 1u * BMAT;
    float* Y   = mats + 2u * BMAT;
    float* Z   = mats + 3u * BMAT;
    float* Y2  = mats + 4u * BMAT;
    float* Z2  = mats + 5u * BMAT;
    float* ZYt = mats + 6u * BMAT;
    float* zz  = mats + 7u * BMAT;
    float* LLT = mats + 8u * BMAT;

    float* bn_mean = small;
    float* bn_rstd = small + 256;
    float* rowmean = small + 512;
    float* tr      = small + 512 + NB * DD;

    const dim3 gs(3, 1, NB);

    // Stage 1: conv + BN + ReLU
    conv_gemm<<<dim3(7, 2, NB), 256>>>(x, w, y);
    bn_stats<<<DD, 256>>>(y, bn_mean, bn_rstd);
    bn_apply<<<NB * DD, 256>>>(y, bn_mean, bn_rstd, gamma, beta, rowmean);

    // Stage 2: covariance + trace normalize (Cn == normalized C == sym_C)
    cov_sym<<<gs, 256>>>(y, rowmean, Cn);
    tracek<<<NB, 256>>>(Cn, tr);
    scalek<<<BMAT / 256, 256>>>(Cn, tr);

    // Stage 3: LLT = inv_sqrtm(Cn + Ij)^2
    run_inv(Cn, jitter, zz, tr, A, Y, Z, Y2, Z2, ZYt);
    bgemm_sym<<<gs, 256>>>(zz, zz, LLT, tr, 0, nullptr, 0.f);

    // Stage 4: SICE loop (i=2 has dec==0 -> exact identity, skipped)
    for (int i = 0; i < 2; i++) {
        run_inv(LLT, jitter, zz, tr, A, Y, Z, Y2, Z2, ZYt);
        const float dec = 5.0f * (1.0f - (float)i / 2.0f);
        bgemm_sym<<<gs, 256>>>(zz, zz, LLT, tr, 3, Cn, dec);
    }

    // Stage 5: final trace normalization + triuvec
    tracek<<<NB, 256>>>(LLT, tr);
    gather_out<<<dim3(DD, NB), 256>>>(LLT, tr, out);
}

// round 4
// speedup vs baseline: 1.4214x; 1.4214x over previous
#include <cuda_runtime.h>

#define NB   32
#define DD   256
#define MMs  784
#define CINc 2048
#define MAT  (DD*DD)          // 65536
#define BMAT (NB*MAT)         // 2,097,152
#define KC   16               // K chunk

typedef unsigned long long ull;

// Scratch (device globals; no allocation anywhere)
__device__ float g_y[NB*DD*MMs];      // BN'd ReLU'd activations [b][d][m]
__device__ float g_mats[9u*BMAT];     // 9 batched 256x256 buffers
__device__ float g_small[16384];      // bn stats, rowmean, tr

// ---------------------------------------------------------------------------
__device__ __forceinline__ float warpReduce(float v) {
    #pragma unroll
    for (int o = 16; o; o >>= 1) v += __shfl_down_sync(0xffffffffu, v, o);
    return v;
}

__device__ __forceinline__ ull dup2(float v) {
    unsigned u = __float_as_uint(v);
    ull r;
    asm("mov.b64 %0, {%1, %1};" : "=l"(r) : "r"(u));
    return r;
}
__device__ __forceinline__ void unpack2(ull p, float& lo, float& hi) {
    unsigned a, b;
    asm("mov.b64 {%0, %1}, %2;" : "=r"(a), "=r"(b) : "l"(p));
    lo = __uint_as_float(a); hi = __uint_as_float(b);
}
#define FFMA2(d, a, b) asm("fma.rn.f32x2 %0, %1, %2, %0;" : "+l"(d) : "l"(a), "l"(b))

// map upper-triangular tile index t in [0,10) -> (ti,tj), ti<=tj, 4x4 tiles
__device__ __forceinline__ void tilemap(int t, int& ti, int& tj) {
    if (t < 4)      { ti = 0; tj = t; }
    else if (t < 7) { ti = 1; tj = t - 3; }
    else if (t < 9) { ti = 2; tj = t - 5; }
    else            { ti = 3; tj = 3; }
}

// ===========================================================================
// Core: 64x64 tile, 128 threads, 8 rows x 4 cols per thread, f32x2 packed.
// As2: A duplicated {v,v} per element, ull [KC][66], indexed [k][row]
//      (pitch 66 ull = 528B; 16B aligned; tr8*8 reads are 2-addr broadcast)
// Bs : plain floats [KC][68], indexed [k][col]; thread reads ulonglong2 at
//      byte 16*tc -> 16 threads x 16B contiguous = conflict-free.
// Per kk: 4 LDS.128 (A) + 1 LDS.128 (B) + 16 FFMA2 = 21 issues / 64 FLOP.
// ===========================================================================
#define GEMM_COMPUTE2(AsB, BsB)                                                \
    {                                                                          \
        _Pragma("unroll")                                                      \
        for (int kk = 0; kk < KC; kk++) {                                      \
            ulonglong2 a01 = *(const ulonglong2*)&AsB[kk][tr8 * 8 + 0];        \
            ulonglong2 a23 = *(const ulonglong2*)&AsB[kk][tr8 * 8 + 2];        \
            ulonglong2 a45 = *(const ulonglong2*)&AsB[kk][tr8 * 8 + 4];        \
            ulonglong2 a67 = *(const ulonglong2*)&AsB[kk][tr8 * 8 + 6];        \
            ulonglong2 bq  = *(const ulonglong2*)&BsB[kk][tc * 4];             \
            ull ar[8] = {a01.x, a01.y, a23.x, a23.y, a45.x, a45.y, a67.x, a67.y};\
            _Pragma("unroll")                                                  \
            for (int i = 0; i < 8; i++) {                                      \
                FFMA2(acc2[i][0], ar[i], bq.x);                                \
                FFMA2(acc2[i][1], ar[i], bq.y);                                \
            }                                                                  \
        }                                                                      \
    }

// ---------------------------------------------------------------------------
// conv 1x1 GEMM: y[b][d][m] = sum_c w[d][c] * x[b][c][m]
// grid (13, 4, NB), 128 threads
// ---------------------------------------------------------------------------
__global__ __launch_bounds__(128, 4) void conv_gemm(
    const float* __restrict__ x, const float* __restrict__ w, float* __restrict__ y)
{
    const int b  = blockIdx.z;
    const int m0 = blockIdx.y * 64;
    const int n0 = blockIdx.x * 64;
    const float* Ap = w;
    const float* Bp = x + (size_t)b * CINc * MMs;
    float* Dp = y + (size_t)b * DD * MMs;

    __shared__ __align__(16) ull   As2[2][KC][66];
    __shared__ __align__(16) float Bs [2][KC][68];
    const int tid = threadIdx.x;
    const int tc = tid & 15, tr8 = tid >> 4;

    float4 pa[2], pb[2];
    ull acc2[8][2] = {};

    // prologue chunk 0
    #pragma unroll
    for (int h = 0; h < 2; h++) {
        int fi = tid + 128 * h;
        int row = fi >> 2, q = fi & 3;
        pa[h] = *(const float4*)(Ap + (size_t)(m0 + row) * CINc + q * 4);
        int kr = fi >> 4, nc = fi & 15;
        int col = n0 + nc * 4;
        pb[h] = (col < MMs) ? *(const float4*)(Bp + (size_t)kr * MMs + col)
                            : make_float4(0.f, 0.f, 0.f, 0.f);
    }
    #pragma unroll
    for (int h = 0; h < 2; h++) {
        int fi = tid + 128 * h;
        int row = fi >> 2, q = fi & 3;
        As2[0][q*4+0][row] = dup2(pa[h].x); As2[0][q*4+1][row] = dup2(pa[h].y);
        As2[0][q*4+2][row] = dup2(pa[h].z); As2[0][q*4+3][row] = dup2(pa[h].w);
        int kr = fi >> 4, nc = fi & 15;
        *(float4*)&Bs[0][kr][nc*4] = pb[h];
    }
    __syncthreads();

    const int NCH = CINc / KC;   // 128
    for (int ch = 0; ch < NCH; ch++) {
        const int buf = ch & 1;
        if (ch + 1 < NCH) {
            const int k0 = (ch + 1) * KC;
            #pragma unroll
            for (int h = 0; h < 2; h++) {
                int fi = tid + 128 * h;
                int row = fi >> 2, q = fi & 3;
                pa[h] = *(const float4*)(Ap + (size_t)(m0 + row) * CINc + k0 + q * 4);
                int kr = fi >> 4, nc = fi & 15;
                int col = n0 + nc * 4;
                pb[h] = (col < MMs) ? *(const float4*)(Bp + (size_t)(k0 + kr) * MMs + col)
                                    : make_float4(0.f, 0.f, 0.f, 0.f);
            }
        }
        GEMM_COMPUTE2(As2[buf], Bs[buf]);
        if (ch + 1 < NCH) {
            const int nb = buf ^ 1;
            #pragma unroll
            for (int h = 0; h < 2; h++) {
                int fi = tid + 128 * h;
                int row = fi >> 2, q = fi & 3;
                As2[nb][q*4+0][row] = dup2(pa[h].x); As2[nb][q*4+1][row] = dup2(pa[h].y);
                As2[nb][q*4+2][row] = dup2(pa[h].z); As2[nb][q*4+3][row] = dup2(pa[h].w);
                int kr = fi >> 4, nc = fi & 15;
                *(float4*)&Bs[nb][kr][nc*4] = pb[h];
            }
            __syncthreads();
        }
    }

    #pragma unroll
    for (int i = 0; i < 8; i++) {
        const int r = m0 + tr8 * 8 + i;
        const int c = n0 + tc * 4;
        float v[4];
        unpack2(acc2[i][0], v[0], v[1]);
        unpack2(acc2[i][1], v[2], v[3]);
        if (c < MMs)
            *(float4*)(Dp + (size_t)r * MMs + c) = make_float4(v[0], v[1], v[2], v[3]);
    }
}

// ---------------------------------------------------------------------------
// BN stats over (b, m) per channel d
// ---------------------------------------------------------------------------
__global__ void bn_stats(const float* __restrict__ y, float* __restrict__ mean,
                         float* __restrict__ rstd)
{
    const int d = blockIdx.x;
    const int t = threadIdx.x;
    float s = 0.f, s2 = 0.f;
    for (int b = 0; b < NB; b++) {
        const float* p = y + (size_t)b * DD * MMs + (size_t)d * MMs;
        for (int m = t; m < MMs; m += 256) { float v = p[m]; s += v; s2 = fmaf(v, v, s2); }
    }
    __shared__ float sh1[8], sh2[8];
    const int lane = t & 31, wid = t >> 5;
    s = warpReduce(s); s2 = warpReduce(s2);
    if (lane == 0) { sh1[wid] = s; sh2[wid] = s2; }
    __syncthreads();
    if (wid == 0) {
        s  = (lane < 8) ? sh1[lane] : 0.f;
        s2 = (lane < 8) ? sh2[lane] : 0.f;
        s = warpReduce(s); s2 = warpReduce(s2);
        if (lane == 0) {
            const float N = (float)(NB * MMs);
            float mu  = s / N;
            float var = s2 / N - mu * mu;
            mean[d] = mu;
            rstd[d] = rsqrtf(var + 1e-5f);
        }
    }
}

// ---------------------------------------------------------------------------
// BN apply + ReLU (in place) + per-(b,d) row mean
// ---------------------------------------------------------------------------
__global__ void bn_apply(float* __restrict__ y, const float* __restrict__ mean,
                         const float* __restrict__ rstd, const float* __restrict__ gamma,
                         const float* __restrict__ beta, float* __restrict__ rowmean)
{
    const int bd = blockIdx.x;
    const int d  = bd & (DD - 1);
    float* p = y + (size_t)bd * MMs;
    const float mu = mean[d], rs = rstd[d], g = gamma[d], be = beta[d];
    const int t = threadIdx.x;
    float s = 0.f;
    for (int m = t; m < MMs; m += 256) {
        float v = fmaf((p[m] - mu) * rs, g, be);
        v = fmaxf(v, 0.f);
        p[m] = v;
        s += v;
    }
    __shared__ float sh[8];
    const int lane = t & 31, wid = t >> 5;
    s = warpReduce(s);
    if (lane == 0) sh[wid] = s;
    __syncthreads();
    if (wid == 0) {
        s = (lane < 8) ? sh[lane] : 0.f;
        s = warpReduce(s);
        if (lane == 0) rowmean[bd] = s * (1.0f / MMs);
    }
}

// ---------------------------------------------------------------------------
// Covariance (symmetric, upper 64x64 tiles, exact mirror):
// C[b] = (Y Y^T)/784 - mu mu^T.   grid (10, 1, NB), 128 threads
// ---------------------------------------------------------------------------
__global__ __launch_bounds__(128, 4) void cov_sym(
    const float* __restrict__ y, const float* __restrict__ rowmean, float* __restrict__ C)
{
    const int b = blockIdx.z;
    int ti, tj; tilemap(blockIdx.x, ti, tj);
    const int i0 = ti * 64, j0 = tj * 64;
    const float* Yb = y + (size_t)b * DD * MMs;

    __shared__ __align__(16) ull   As2[2][KC][66];
    __shared__ __align__(16) float Bs [2][KC][68];
    const int tid = threadIdx.x;
    const int tc = tid & 15, tr8 = tid >> 4;

    float4 pa[2], pb[2];
    ull acc2[8][2] = {};

    #pragma unroll
    for (int h = 0; h < 2; h++) {
        int fi = tid + 128 * h;
        int row = fi >> 2, q = fi & 3;
        pa[h] = *(const float4*)(Yb + (size_t)(i0 + row) * MMs + q * 4);
        pb[h] = *(const float4*)(Yb + (size_t)(j0 + row) * MMs + q * 4);
    }
    #pragma unroll
    for (int h = 0; h < 2; h++) {
        int fi = tid + 128 * h;
        int row = fi >> 2, q = fi & 3;
        As2[0][q*4+0][row] = dup2(pa[h].x); As2[0][q*4+1][row] = dup2(pa[h].y);
        As2[0][q*4+2][row] = dup2(pa[h].z); As2[0][q*4+3][row] = dup2(pa[h].w);
        Bs[0][q*4+0][row] = pb[h].x; Bs[0][q*4+1][row] = pb[h].y;
        Bs[0][q*4+2][row] = pb[h].z; Bs[0][q*4+3][row] = pb[h].w;
    }
    __syncthreads();

    const int NCH = MMs / KC;   // 49
    for (int ch = 0; ch < NCH; ch++) {
        const int buf = ch & 1;
        if (ch + 1 < NCH) {
            const int k0 = (ch + 1) * KC;
            #pragma unroll
            for (int h = 0; h < 2; h++) {
                int fi = tid + 128 * h;
                int row = fi >> 2, q = fi & 3;
                pa[h] = *(const float4*)(Yb + (size_t)(i0 + row) * MMs + k0 + q * 4);
                pb[h] = *(const float4*)(Yb + (size_t)(j0 + row) * MMs + k0 + q * 4);
            }
        }
        GEMM_COMPUTE2(As2[buf], Bs[buf]);
        if (ch + 1 < NCH) {
            const int nb = buf ^ 1;
            #pragma unroll
            for (int h = 0; h < 2; h++) {
                int fi = tid + 128 * h;
                int row = fi >> 2, q = fi & 3;
                As2[nb][q*4+0][row] = dup2(pa[h].x); As2[nb][q*4+1][row] = dup2(pa[h].y);
                As2[nb][q*4+2][row] = dup2(pa[h].z); As2[nb][q*4+3][row] = dup2(pa[h].w);
                Bs[nb][q*4+0][row] = pb[h].x; Bs[nb][q*4+1][row] = pb[h].y;
                Bs[nb][q*4+2][row] = pb[h].z; Bs[nb][q*4+3][row] = pb[h].w;
            }
            __syncthreads();
        }
    }

    const float invM = 1.0f / (float)MMs;
    const float* mu = rowmean + b * DD;
    float* Cb = C + (size_t)b * MAT;
    #pragma unroll
    for (int i = 0; i < 8; i++) {
        const int r = i0 + tr8 * 8 + i;
        const float mi = mu[r];
        const int c0 = j0 + tc * 4;
        float v[4];
        unpack2(acc2[i][0], v[0], v[1]);
        unpack2(acc2[i][1], v[2], v[3]);
        #pragma unroll
        for (int j = 0; j < 4; j++) v[j] = v[j] * invM - mi * mu[c0 + j];
        *(float4*)(Cb + (size_t)r * DD + c0) = make_float4(v[0], v[1], v[2], v[3]);
        if (ti != tj) {
            #pragma unroll
            for (int j = 0; j < 4; j++) Cb[(size_t)(c0+j) * DD + r] = v[j];
        }
    }
}

// ---------------------------------------------------------------------------
// Batched symmetric-output 256^3 GEMM, upper 64x64 tiles, mirrored.
// epi 0: D = P;  1: D = 1.5I - 0.5P;  2: D = P*rsqrt(tr);
// 3: fused SICE: L = sice(L, Cn - P, dec)     grid (10, 1, NB), 128 threads
// ---------------------------------------------------------------------------
__device__ __forceinline__ float sice_f(float L, float g12, float dec)
{
    float lp = fmaxf(L, 0.f);
    float lm = fmaxf(-L, 0.f);
    lp = fmaxf(lp - dec * (g12 + 0.07f), 0.f);
    lm = fmaxf(lm - dec * (-g12 + 0.07f), 0.f);
    return lp - lm;
}

#define GEMM256_LOAD(k0)                                                       \
    {                                                                          \
        _Pragma("unroll")                                                      \
        for (int h = 0; h < 2; h++) {                                          \
            int fi = tid + 128 * h;                                            \
            int row = fi >> 2, q = fi & 3;                                     \
            pa[h] = *(const float4*)(Ap + (size_t)(m0 + row) * DD + (k0) + q * 4);\
            int kr = fi >> 4, nc = fi & 15;                                    \
            pb[h] = *(const float4*)(Bp + (size_t)((k0) + kr) * DD + n0 + nc * 4);\
        }                                                                      \
    }
#define GEMM256_STORE(nb)                                                      \
    {                                                                          \
        _Pragma("unroll")                                                      \
        for (int h = 0; h < 2; h++) {                                          \
            int fi = tid + 128 * h;                                            \
            int row = fi >> 2, q = fi & 3;                                     \
            As2[nb][q*4+0][row] = dup2(pa[h].x); As2[nb][q*4+1][row] = dup2(pa[h].y);\
            As2[nb][q*4+2][row] = dup2(pa[h].z); As2[nb][q*4+3][row] = dup2(pa[h].w);\
            int kr = fi >> 4, nc = fi & 15;                                    \
            *(float4*)&Bs[nb][kr][nc*4] = pb[h];                               \
        }                                                                      \
    }

__global__ __launch_bounds__(128, 4) void bgemm_sym(
    const float* __restrict__ Ab, const float* __restrict__ Bb, float* __restrict__ Db,
    const float* __restrict__ tr, int epi, const float* __restrict__ Cn, float dec)
{
    const int b = blockIdx.z;
    int ti, tj; tilemap(blockIdx.x, ti, tj);
    const int m0 = ti * 64, n0 = tj * 64;
    const float* Ap = Ab + (size_t)b * MAT;
    const float* Bp = Bb + (size_t)b * MAT;
    float* Dp = Db + (size_t)b * MAT;

    __shared__ __align__(16) ull   As2[2][KC][66];
    __shared__ __align__(16) float Bs [2][KC][68];
    const int tid = threadIdx.x;
    const int tc = tid & 15, tr8 = tid >> 4;

    float4 pa[2], pb[2];
    ull acc2[8][2] = {};

    GEMM256_LOAD(0);
    GEMM256_STORE(0);
    __syncthreads();

    const int NCH = DD / KC;   // 16
    for (int ch = 0; ch < NCH; ch++) {
        const int buf = ch & 1;
        if (ch + 1 < NCH) GEMM256_LOAD((ch + 1) * KC);
        GEMM_COMPUTE2(As2[buf], Bs[buf]);
        if (ch + 1 < NCH) {
            const int nb = buf ^ 1;
            GEMM256_STORE(nb);
            __syncthreads();
        }
    }

    const float rs = (epi == 2) ? rsqrtf(tr[b]) : 1.0f;
    const float* Cb = (epi == 3) ? (Cn + (size_t)b * MAT) : nullptr;
    #pragma unroll
    for (int i = 0; i < 8; i++) {
        const int r = m0 + tr8 * 8 + i;
        const int c0 = n0 + tc * 4;
        float v[4];
        unpack2(acc2[i][0], v[0], v[1]);
        unpack2(acc2[i][1], v[2], v[3]);
        if (epi == 1) {
            #pragma unroll
            for (int j = 0; j < 4; j++)
                v[j] = ((r == c0 + j) ? 1.5f : 0.0f) - 0.5f * v[j];
        } else if (epi == 2) {
            #pragma unroll
            for (int j = 0; j < 4; j++) v[j] *= rs;
        } else if (epi == 3) {
            #pragma unroll
            for (int j = 0; j < 4; j++) {
                float Lv = Dp[(size_t)r * DD + c0 + j];
                float g  = Cb[(size_t)r * DD + c0 + j] - v[j];
                v[j] = sice_f(Lv, g, dec);
            }
        }
        *(float4*)(Dp + (size_t)r * DD + c0) = make_float4(v[0], v[1], v[2], v[3]);
        if (ti != tj) {
            #pragma unroll
            for (int j = 0; j < 4; j++) Dp[(size_t)(c0+j) * DD + r] = v[j];
        }
    }
}

// ---------------------------------------------------------------------------
// Fused pair: z<NB -> D1 = A1@B1 ; z>=NB -> D2 = A2@B2 (symmetric, epi 0)
// grid (10, 1, 2*NB), 128 threads
// ---------------------------------------------------------------------------
__global__ __launch_bounds__(128, 4) void bgemm_pair(
    const float* __restrict__ A1, const float* __restrict__ B1, float* __restrict__ D1,
    const float* __restrict__ A2, const float* __restrict__ B2, float* __restrict__ D2)
{
    const int z = blockIdx.z;
    const int b = z & (NB - 1);
    const bool second = z >= NB;
    const float* Ap = (second ? A2 : A1) + (size_t)b * MAT;
    const float* Bp = (second ? B2 : B1) + (size_t)b * MAT;
    float* Dp = (second ? D2 : D1) + (size_t)b * MAT;

    int ti, tj; tilemap(blockIdx.x, ti, tj);
    const int m0 = ti * 64, n0 = tj * 64;

    __shared__ __align__(16) ull   As2[2][KC][66];
    __shared__ __align__(16) float Bs [2][KC][68];
    const int tid = threadIdx.x;
    const int tc = tid & 15, tr8 = tid >> 4;

    float4 pa[2], pb[2];
    ull acc2[8][2] = {};

    GEMM256_LOAD(0);
    GEMM256_STORE(0);
    __syncthreads();

    const int NCH = DD / KC;
    for (int ch = 0; ch < NCH; ch++) {
        const int buf = ch & 1;
        if (ch + 1 < NCH) GEMM256_LOAD((ch + 1) * KC);
        GEMM_COMPUTE2(As2[buf], Bs[buf]);
        if (ch + 1 < NCH) {
            const int nb = buf ^ 1;
            GEMM256_STORE(nb);
            __syncthreads();
        }
    }

    #pragma unroll
    for (int i = 0; i < 8; i++) {
        const int r = m0 + tr8 * 8 + i;
        const int c0 = n0 + tc * 4;
        float v[4];
        unpack2(acc2[i][0], v[0], v[1]);
        unpack2(acc2[i][1], v[2], v[3]);
        *(float4*)(Dp + (size_t)r * DD + c0) = make_float4(v[0], v[1], v[2], v[3]);
        if (ti != tj) {
            #pragma unroll
            for (int j = 0; j < 4; j++) Dp[(size_t)(c0+j) * DD + r] = v[j];
        }
    }
}

// ---------------------------------------------------------------------------
// small kernels
// ---------------------------------------------------------------------------
__global__ void tracek(const float* __restrict__ X, float* __restrict__ tr)
{
    const int b = blockIdx.x;
    const int t = threadIdx.x;
    float v = X[(size_t)b * MAT + t * 257];
    __shared__ float sh[8];
    const int lane = t & 31, wid = t >> 5;
    v = warpReduce(v);
    if (lane == 0) sh[wid] = v;
    __syncthreads();
    if (wid == 0) {
        v = (lane < 8) ? sh[lane] : 0.f;
        v = warpReduce(v);
        if (lane == 0) tr[b] = v;
    }
}

__global__ void tracek_j(const float* __restrict__ X, const float* __restrict__ jitter,
                         float* __restrict__ tr)
{
    const int b = blockIdx.x;
    const int t = threadIdx.x;
    float v = X[(size_t)b * MAT + t * 257] + 1e-10f + 1e-9f * jitter[t];
    __shared__ float sh[8];
    const int lane = t & 31, wid = t >> 5;
    v = warpReduce(v);
    if (lane == 0) sh[wid] = v;
    __syncthreads();
    if (wid == 0) {
        v = (lane < 8) ? sh[lane] : 0.f;
        v = warpReduce(v);
        if (lane == 0) tr[b] = v;
    }
}

__global__ void scalek(float* __restrict__ C, const float* __restrict__ tr)
{
    const int idx = blockIdx.x * 256 + threadIdx.x;
    C[idx] *= (1.0f / tr[idx >> 16]);
}

// A = (S + Ij)/tr[b];  ZY0 = 0.5*(3I - A)
__global__ void prep_ns(const float* __restrict__ S, const float* __restrict__ jitter,
                        const float* __restrict__ tr, float* __restrict__ A,
                        float* __restrict__ ZY)
{
    const int idx = blockIdx.x * 256 + threadIdx.x;
    const int b = idx >> 16, rc = idx & 65535, r = rc >> 8, c = rc & 255;
    float v = S[idx];
    if (r == c) v += 1e-10f + 1e-9f * jitter[r];
    float a = v * (1.0f / tr[b]);
    A[idx] = a;
    ZY[idx] = (r == c ? 1.5f : 0.0f) - 0.5f * a;
}

__global__ void gather_out(const float* __restrict__ L, const float* __restrict__ tr,
                           float* __restrict__ out)
{
    const int b = blockIdx.y, i = blockIdx.x, j = threadIdx.x;
    if (j < i) return;
    const float s = rsqrtf(tr[b]);
    const int k = i * 256 - (i * (i - 1)) / 2 + (j - i);
    out[(size_t)b * 32896 + k] = L[(size_t)b * MAT + i * 256 + j] * s;
}

// ---------------------------------------------------------------------------
// Host orchestration
// ---------------------------------------------------------------------------
static void run_inv(const float* S, const float* jitter, float* zz, float* tr,
                    float* A, float* Y, float* Z, float* Y2, float* Z2, float* ZYt)
{
    const dim3 gs(10, 1, NB);
    tracek_j<<<NB, 256>>>(S, jitter, tr);
    prep_ns<<<BMAT / 256, 256>>>(S, jitter, tr, A, Z);    // Z = ZY0
    bgemm_sym<<<gs, 128>>>(A, Z, Y, tr, 0, nullptr, 0.f); // Y = A @ ZY0
    float *Yc = Y, *Zc = Z, *Ya = Y2, *Za = Z2;
    for (int it = 0; it < 5; it++) {
        bgemm_sym<<<gs, 128>>>(Zc, Yc, ZYt, tr, 1, nullptr, 0.f);   // ZY = 1.5I-0.5 Z@Y
        bgemm_pair<<<dim3(10, 1, 2 * NB), 128>>>(Yc, ZYt, Ya, ZYt, Zc, Za);
        float* t1 = Yc; Yc = Ya; Ya = t1;
        float* t2 = Zc; Zc = Za; Za = t2;
    }
    bgemm_sym<<<gs, 128>>>(Zc, Yc, ZYt, tr, 1, nullptr, 0.f);
    bgemm_sym<<<gs, 128>>>(ZYt, Zc, zz, tr, 2, nullptr, 0.f);       // * tr^-0.5
}

extern "C" void kernel_launch(void* const* d_in, const int* in_sizes, int n_in,
                              void* d_out, int out_size)
{
    (void)in_sizes; (void)n_in; (void)out_size;
    const float* x      = (const float*)d_in[0];
    const float* w      = (const float*)d_in[1];
    const float* gamma  = (const float*)d_in[2];
    const float* beta   = (const float*)d_in[3];
    const float* jitter = (const float*)d_in[4];
    float* out = (float*)d_out;

    float *y, *mats, *small;
    cudaGetSymbolAddress((void**)&y, g_y);
    cudaGetSymbolAddress((void**)&mats, g_mats);
    cudaGetSymbolAddress((void**)&small, g_small);

    float* Cn  = mats + 0u * BMAT;
    float* A   = mats + 1u * BMAT;
    float* Y   = mats + 2u * BMAT;
    float* Z   = mats + 3u * BMAT;
    float* Y2  = mats + 4u * BMAT;
    float* Z2  = mats + 5u * BMAT;
    float* ZYt = mats + 6u * BMAT;
    float* zz  = mats + 7u * BMAT;
    float* LLT = mats + 8u * BMAT;

    float* bn_mean = small;
    float* bn_rstd = small + 256;
    float* rowmean = small + 512;
    float* tr      = small + 512 + NB * DD;

    const dim3 gs(10, 1, NB);

    // Stage 1: conv + BN + ReLU
    conv_gemm<<<dim3(13, 4, NB), 128>>>(x, w, y);
    bn_stats<<<DD, 256>>>(y, bn_mean, bn_rstd);
    bn_apply<<<NB * DD, 256>>>(y, bn_mean, bn_rstd, gamma, beta, rowmean);

    // Stage 2: covariance + trace normalize (Cn == normalized C == sym_C)
    cov_sym<<<gs, 128>>>(y, rowmean, Cn);
    tracek<<<NB, 256>>>(Cn, tr);
    scalek<<<BMAT / 256, 256>>>(Cn, tr);

    // Stage 3: LLT = inv_sqrtm(Cn + Ij)^2
    run_inv(Cn, jitter, zz, tr, A, Y, Z, Y2, Z2, ZYt);
    bgemm_sym<<<gs, 128>>>(zz, zz, LLT, tr, 0, nullptr, 0.f);

    // Stage 4: SICE loop (i=2 has dec==0 -> exact identity, skipped)
    for (int i = 0; i < 2; i++) {
        run_inv(LLT, jitter, zz, tr, A, Y, Z, Y2, Z2, ZYt);
        const float dec = 5.0f * (1.0f - (float)i / 2.0f);
        bgemm_sym<<<gs, 128>>>(zz, zz, LLT, tr, 3, Cn, dec);
    }

    // Stage 5: final trace normalization + triuvec
    tracek<<<NB, 256>>>(LLT, tr);
    gather_out<<<dim3(DD, NB), 256>>>(LLT, tr, out);
}

// round 5
// speedup vs baseline: 1.7207x; 1.2105x over previous
#include <cuda_runtime.h>

#define NB   32
#define DD   256
#define MMs  784
#define CINc 2048
#define MAT  (DD*DD)          // 65536
#define BMAT (NB*MAT)         // 2,097,152
#define KC   16               // K chunk

// Scratch (device globals; no allocation anywhere)
__device__ float g_y[NB*DD*MMs];      // BN'd ReLU'd activations [b][d][m]
__device__ float g_mats[9u*BMAT];     // 9 batched 256x256 buffers
__device__ float g_small[16384];

// g_small layout (floats):
//   [0,256)      bn_mean
//   [256,512)    bn_rstd
//   [512,8704)   rowmean (NB*DD)
//   [8704,8736)  tr0   (trace of raw C, per b)
//   [8736,8768)  tr_now (current NS normA, per b)
//   [8768]       jc  = sum(1e-10 + 1e-9*jitter)
//   [8772,8900)  trp (trace partials, NB*4)

// ---------------------------------------------------------------------------
__device__ __forceinline__ float warpReduce(float v) {
    #pragma unroll
    for (int o = 16; o; o >>= 1) v += __shfl_down_sync(0xffffffffu, v, o);
    return v;
}

// map upper-triangular tile index t in [0,10) -> (ti,tj), ti<=tj, 4x4 tiles
__device__ __forceinline__ void tilemap(int t, int& ti, int& tj) {
    if (t < 4)      { ti = 0; tj = t; }
    else if (t < 7) { ti = 1; tj = t - 3; }
    else if (t < 9) { ti = 2; tj = t - 5; }
    else            { ti = 3; tj = 3; }
}

__device__ __forceinline__ float sice_f(float L, float g12, float dec)
{
    float lp = fmaxf(L, 0.f);
    float lm = fmaxf(-L, 0.f);
    lp = fmaxf(lp - dec * (g12 + 0.07f), 0.f);
    lm = fmaxf(lm - dec * (-g12 + 0.07f), 0.f);
    return lp - lm;
}

// ===========================================================================
// R2 scalar GEMM compute (64x64 tile, 128 lanes, 8x4 microtile), array form
// ===========================================================================
#define GEMM_COMPUTE(AsB, BsB)                                                 \
    {                                                                          \
        _Pragma("unroll")                                                      \
        for (int kk = 0; kk < KC; kk++) {                                      \
            float4 a0 = *(const float4*)(&(AsB)[kk][tr8 * 8]);                 \
            float4 a1 = *(const float4*)(&(AsB)[kk][tr8 * 8 + 4]);             \
            float4 bv = *(const float4*)(&(BsB)[kk][tc * 4]);                  \
            float ar[8] = {a0.x,a0.y,a0.z,a0.w,a1.x,a1.y,a1.z,a1.w};           \
            float br[4] = {bv.x,bv.y,bv.z,bv.w};                               \
            _Pragma("unroll")                                                  \
            for (int i = 0; i < 8; i++)                                        \
                _Pragma("unroll")                                              \
                for (int j = 0; j < 4; j++)                                    \
                    acc[i][j] = fmaf(ar[i], br[j], acc[i][j]);                 \
        }                                                                      \
    }

// pointer-region variant for split-K kernels: base points to float[KC][68]
#define GEMM_COMPUTE_P(pA, pB)                                                 \
    {                                                                          \
        _Pragma("unroll")                                                      \
        for (int kk = 0; kk < KC; kk++) {                                      \
            float4 a0 = *(const float4*)((pA) + kk * 68 + tr8 * 8);            \
            float4 a1 = *(const float4*)((pA) + kk * 68 + tr8 * 8 + 4);        \
            float4 bv = *(const float4*)((pB) + kk * 68 + tc * 4);             \
            float ar[8] = {a0.x,a0.y,a0.z,a0.w,a1.x,a1.y,a1.z,a1.w};           \
            float br[4] = {bv.x,bv.y,bv.z,bv.w};                               \
            _Pragma("unroll")                                                  \
            for (int i = 0; i < 8; i++)                                        \
                _Pragma("unroll")                                              \
                for (int j = 0; j < 4; j++)                                    \
                    acc[i][j] = fmaf(ar[i], br[j], acc[i][j]);                 \
        }                                                                      \
    }

// ---------------------------------------------------------------------------
// conv 1x1 GEMM (R2 verbatim): y[b][d][m] = sum_c w[d][c] * x[b][c][m]
// grid (13, 4, NB), 128 threads
// ---------------------------------------------------------------------------
__global__ void conv_gemm(
    const float* __restrict__ x, const float* __restrict__ w, float* __restrict__ y)
{
    const int b  = blockIdx.z;
    const int m0 = blockIdx.y * 64;
    const int n0 = blockIdx.x * 64;
    const float* Ap = w;
    const float* Bp = x + (size_t)b * CINc * MMs;
    float* Dp = y + (size_t)b * DD * MMs;

    __shared__ float As[2][KC][68];
    __shared__ float Bs[2][KC][68];
    const int tid = threadIdx.x;
    const int tc = tid & 15, tr8 = tid >> 4;

    float4 pa[2], pb[2];
    float acc[8][4] = {};

    #pragma unroll
    for (int h = 0; h < 2; h++) {
        int fi = tid + 128 * h;
        int row = fi >> 2, q = fi & 3;
        pa[h] = *(const float4*)(Ap + (size_t)(m0 + row) * CINc + q * 4);
        int kr = fi >> 4, nc = fi & 15;
        int col = n0 + nc * 4;
        pb[h] = (col < MMs) ? *(const float4*)(Bp + (size_t)kr * MMs + col)
                            : make_float4(0.f, 0.f, 0.f, 0.f);
    }
    #pragma unroll
    for (int h = 0; h < 2; h++) {
        int fi = tid + 128 * h;
        int row = fi >> 2, q = fi & 3;
        As[0][q*4+0][row] = pa[h].x; As[0][q*4+1][row] = pa[h].y;
        As[0][q*4+2][row] = pa[h].z; As[0][q*4+3][row] = pa[h].w;
        int kr = fi >> 4, nc = fi & 15;
        *(float4*)&Bs[0][kr][nc*4] = pb[h];
    }
    __syncthreads();

    const int NCH = CINc / KC;
    for (int ch = 0; ch < NCH; ch++) {
        const int buf = ch & 1;
        if (ch + 1 < NCH) {
            const int k0 = (ch + 1) * KC;
            #pragma unroll
            for (int h = 0; h < 2; h++) {
                int fi = tid + 128 * h;
                int row = fi >> 2, q = fi & 3;
                pa[h] = *(const float4*)(Ap + (size_t)(m0 + row) * CINc + k0 + q * 4);
                int kr = fi >> 4, nc = fi & 15;
                int col = n0 + nc * 4;
                pb[h] = (col < MMs) ? *(const float4*)(Bp + (size_t)(k0 + kr) * MMs + col)
                                    : make_float4(0.f, 0.f, 0.f, 0.f);
            }
        }
        GEMM_COMPUTE(As[buf], Bs[buf]);
        if (ch + 1 < NCH) {
            const int nb = buf ^ 1;
            #pragma unroll
            for (int h = 0; h < 2; h++) {
                int fi = tid + 128 * h;
                int row = fi >> 2, q = fi & 3;
                As[nb][q*4+0][row] = pa[h].x; As[nb][q*4+1][row] = pa[h].y;
                As[nb][q*4+2][row] = pa[h].z; As[nb][q*4+3][row] = pa[h].w;
                int kr = fi >> 4, nc = fi & 15;
                *(float4*)&Bs[nb][kr][nc*4] = pb[h];
            }
            __syncthreads();
        }
    }

    #pragma unroll
    for (int i = 0; i < 8; i++) {
        const int r = m0 + tr8 * 8 + i;
        const int c = n0 + tc * 4;
        if (c < MMs)
            *(float4*)(Dp + (size_t)r * MMs + c) =
                make_float4(acc[i][0], acc[i][1], acc[i][2], acc[i][3]);
    }
}

// ---------------------------------------------------------------------------
// BN stats + apply (R2 verbatim)
// ---------------------------------------------------------------------------
__global__ void bn_stats(const float* __restrict__ y, float* __restrict__ mean,
                         float* __restrict__ rstd)
{
    const int d = blockIdx.x;
    const int t = threadIdx.x;
    float s = 0.f, s2 = 0.f;
    for (int b = 0; b < NB; b++) {
        const float* p = y + (size_t)b * DD * MMs + (size_t)d * MMs;
        for (int m = t; m < MMs; m += 256) { float v = p[m]; s += v; s2 = fmaf(v, v, s2); }
    }
    __shared__ float sh1[8], sh2[8];
    const int lane = t & 31, wid = t >> 5;
    s = warpReduce(s); s2 = warpReduce(s2);
    if (lane == 0) { sh1[wid] = s; sh2[wid] = s2; }
    __syncthreads();
    if (wid == 0) {
        s  = (lane < 8) ? sh1[lane] : 0.f;
        s2 = (lane < 8) ? sh2[lane] : 0.f;
        s = warpReduce(s); s2 = warpReduce(s2);
        if (lane == 0) {
            const float N = (float)(NB * MMs);
            float mu  = s / N;
            float var = s2 / N - mu * mu;
            mean[d] = mu;
            rstd[d] = rsqrtf(var + 1e-5f);
        }
    }
}

__global__ void bn_apply(float* __restrict__ y, const float* __restrict__ mean,
                         const float* __restrict__ rstd, const float* __restrict__ gamma,
                         const float* __restrict__ beta, float* __restrict__ rowmean)
{
    const int bd = blockIdx.x;
    const int d  = bd & (DD - 1);
    float* p = y + (size_t)bd * MMs;
    const float mu = mean[d], rs = rstd[d], g = gamma[d], be = beta[d];
    const int t = threadIdx.x;
    float s = 0.f;
    for (int m = t; m < MMs; m += 256) {
        float v = fmaf((p[m] - mu) * rs, g, be);
        v = fmaxf(v, 0.f);
        p[m] = v;
        s += v;
    }
    __shared__ float sh[8];
    const int lane = t & 31, wid = t >> 5;
    s = warpReduce(s);
    if (lane == 0) sh[wid] = s;
    __syncthreads();
    if (wid == 0) {
        s = (lane < 8) ? sh[lane] : 0.f;
        s = warpReduce(s);
        if (lane == 0) rowmean[bd] = s * (1.0f / MMs);
    }
}

// ---------------------------------------------------------------------------
// Covariance (R2 verbatim): C[b] = (Y Y^T)/784 - mu mu^T, upper tiles+mirror
// grid (10, 1, NB), 128 threads
// ---------------------------------------------------------------------------
__global__ void cov_sym(
    const float* __restrict__ y, const float* __restrict__ rowmean, float* __restrict__ C)
{
    const int b = blockIdx.z;
    int ti, tj; tilemap(blockIdx.x, ti, tj);
    const int i0 = ti * 64, j0 = tj * 64;
    const float* Yb = y + (size_t)b * DD * MMs;

    __shared__ float Is[2][KC][68];
    __shared__ float Js[2][KC][68];
    const int tid = threadIdx.x;
    const int tc = tid & 15, tr8 = tid >> 4;

    float4 pa[2], pb[2];
    float acc[8][4] = {};

    #pragma unroll
    for (int h = 0; h < 2; h++) {
        int fi = tid + 128 * h;
        int row = fi >> 2, q = fi & 3;
        pa[h] = *(const float4*)(Yb + (size_t)(i0 + row) * MMs + q * 4);
        pb[h] = *(const float4*)(Yb + (size_t)(j0 + row) * MMs + q * 4);
    }
    #pragma unroll
    for (int h = 0; h < 2; h++) {
        int fi = tid + 128 * h;
        int row = fi >> 2, q = fi & 3;
        Is[0][q*4+0][row] = pa[h].x; Is[0][q*4+1][row] = pa[h].y;
        Is[0][q*4+2][row] = pa[h].z; Is[0][q*4+3][row] = pa[h].w;
        Js[0][q*4+0][row] = pb[h].x; Js[0][q*4+1][row] = pb[h].y;
        Js[0][q*4+2][row] = pb[h].z; Js[0][q*4+3][row] = pb[h].w;
    }
    __syncthreads();

    const int NCH = MMs / KC;   // 49
    for (int ch = 0; ch < NCH; ch++) {
        const int buf = ch & 1;
        if (ch + 1 < NCH) {
            const int k0 = (ch + 1) * KC;
            #pragma unroll
            for (int h = 0; h < 2; h++) {
                int fi = tid + 128 * h;
                int row = fi >> 2, q = fi & 3;
                pa[h] = *(const float4*)(Yb + (size_t)(i0 + row) * MMs + k0 + q * 4);
                pb[h] = *(const float4*)(Yb + (size_t)(j0 + row) * MMs + k0 + q * 4);
            }
        }
        GEMM_COMPUTE(Is[buf], Js[buf]);
        if (ch + 1 < NCH) {
            const int nb = buf ^ 1;
            #pragma unroll
            for (int h = 0; h < 2; h++) {
                int fi = tid + 128 * h;
                int row = fi >> 2, q = fi & 3;
                Is[nb][q*4+0][row] = pa[h].x; Is[nb][q*4+1][row] = pa[h].y;
                Is[nb][q*4+2][row] = pa[h].z; Is[nb][q*4+3][row] = pa[h].w;
                Js[nb][q*4+0][row] = pb[h].x; Js[nb][q*4+1][row] = pb[h].y;
                Js[nb][q*4+2][row] = pb[h].z; Js[nb][q*4+3][row] = pb[h].w;
            }
            __syncthreads();
        }
    }

    const float invM = 1.0f / (float)MMs;
    const float* mu = rowmean + b * DD;
    float* Cb = C + (size_t)b * MAT;
    #pragma unroll
    for (int i = 0; i < 8; i++) {
        const int r = i0 + tr8 * 8 + i;
        const float mi = mu[r];
        const int c0 = j0 + tc * 4;
        float v[4];
        #pragma unroll
        for (int j = 0; j < 4; j++) v[j] = acc[i][j] * invM - mi * mu[c0 + j];
        *(float4*)(Cb + (size_t)r * DD + c0) = make_float4(v[0], v[1], v[2], v[3]);
        if (ti != tj) {
            #pragma unroll
            for (int j = 0; j < 4; j++) Cb[(size_t)(c0+j) * DD + r] = v[j];
        }
    }
}

// ---------------------------------------------------------------------------
// Split-K batched symmetric 256^3 GEMM. 256 threads: half=tid>>7 owns K half.
// After compute, half 1 dumps acc to smem; half 0 reduces + epilogue + mirror.
// epi 0: D=P; 1: D=1.5I-0.5P; 2: D=P*rsqrt(tr_now[b]); 3: fused SICE.
// Diagonal tiles optionally write plain-trace partials trp[b*4+ti].
// grid (10, 1, NB), 256 threads
// ---------------------------------------------------------------------------
__global__ __launch_bounds__(256, 2) void bgemm_sym(
    const float* __restrict__ Ab, const float* __restrict__ Bb, float* __restrict__ Db,
    const float* __restrict__ tr_now, int epi, const float* __restrict__ Cn, float dec,
    float* __restrict__ trp)
{
    const int b = blockIdx.z;
    int ti, tj; tilemap(blockIdx.x, ti, tj);
    const int m0 = ti * 64, n0 = tj * 64;
    const float* Ap = Ab + (size_t)b * MAT;
    const float* Bp = Bb + (size_t)b * MAT;
    float* Dp = Db + (size_t)b * MAT;

    __shared__ __align__(16) float S[8704];   // [half][buf] A:0..4352, B:4352..8704
    __shared__ float dred[256];

    const int tid = threadIdx.x;
    const int half = tid >> 7, lt = tid & 127;
    const int tc = lt & 15, tr8 = lt >> 4;
    const int kb0 = half * 128;

    float* const SA0 = S + (half * 2 + 0) * 1088;
    float* const SA1 = S + (half * 2 + 1) * 1088;
    float* const SB0 = S + 4352 + (half * 2 + 0) * 1088;
    float* const SB1 = S + 4352 + (half * 2 + 1) * 1088;

    float4 pa[2], pb[2];
    float acc[8][4] = {};

    // prologue: chunk 0 of this half
    #pragma unroll
    for (int h = 0; h < 2; h++) {
        int fi = lt + 128 * h;
        int row = fi >> 2, q = fi & 3;
        pa[h] = *(const float4*)(Ap + (size_t)(m0 + row) * DD + kb0 + q * 4);
        int kr = fi >> 4, nc = fi & 15;
        pb[h] = *(const float4*)(Bp + (size_t)(kb0 + kr) * DD + n0 + nc * 4);
    }
    #pragma unroll
    for (int h = 0; h < 2; h++) {
        int fi = lt + 128 * h;
        int row = fi >> 2, q = fi & 3;
        SA0[(q*4+0)*68+row] = pa[h].x; SA0[(q*4+1)*68+row] = pa[h].y;
        SA0[(q*4+2)*68+row] = pa[h].z; SA0[(q*4+3)*68+row] = pa[h].w;
        int kr = fi >> 4, nc = fi & 15;
        *(float4*)(SB0 + kr*68 + nc*4) = pb[h];
    }
    __syncthreads();

    const int NCHH = 128 / KC;   // 8 chunks per half
    for (int ch = 0; ch < NCHH; ch++) {
        const float* cA = (ch & 1) ? SA1 : SA0;
        const float* cB = (ch & 1) ? SB1 : SB0;
        if (ch + 1 < NCHH) {
            const int k0 = kb0 + (ch + 1) * KC;
            #pragma unroll
            for (int h = 0; h < 2; h++) {
                int fi = lt + 128 * h;
                int row = fi >> 2, q = fi & 3;
                pa[h] = *(const float4*)(Ap + (size_t)(m0 + row) * DD + k0 + q * 4);
                int kr = fi >> 4, nc = fi & 15;
                pb[h] = *(const float4*)(Bp + (size_t)(k0 + kr) * DD + n0 + nc * 4);
            }
        }
        GEMM_COMPUTE_P(cA, cB);
        if (ch + 1 < NCHH) {
            float* nA = (ch & 1) ? SA0 : SA1;
            float* nB = (ch & 1) ? SB0 : SB1;
            #pragma unroll
            for (int h = 0; h < 2; h++) {
                int fi = lt + 128 * h;
                int row = fi >> 2, q = fi & 3;
                nA[(q*4+0)*68+row] = pa[h].x; nA[(q*4+1)*68+row] = pa[h].y;
                nA[(q*4+2)*68+row] = pa[h].z; nA[(q*4+3)*68+row] = pa[h].w;
                int kr = fi >> 4, nc = fi & 15;
                *(float4*)(nB + kr*68 + nc*4) = pb[h];
            }
            __syncthreads();
        }
    }

    __syncthreads();               // all compute done; smem reusable
    if (half == 1) {
        #pragma unroll
        for (int i = 0; i < 8; i++)
            *(float4*)(S + lt * 36 + i * 4) =
                make_float4(acc[i][0], acc[i][1], acc[i][2], acc[i][3]);
    }
    __syncthreads();

    float dsum = 0.f;
    if (half == 0) {
        const float rs = (epi == 2) ? rsqrtf(tr_now[b]) : 1.0f;
        const float* Cb = (epi == 3) ? (Cn + (size_t)b * MAT) : nullptr;
        #pragma unroll
        for (int i = 0; i < 8; i++) {
            float4 o = *(const float4*)(S + lt * 36 + i * 4);
            const int r = m0 + tr8 * 8 + i;
            const int c0 = n0 + tc * 4;
            float v[4] = {acc[i][0] + o.x, acc[i][1] + o.y,
                          acc[i][2] + o.z, acc[i][3] + o.w};
            if (epi == 1) {
                #pragma unroll
                for (int j = 0; j < 4; j++)
                    v[j] = ((r == c0 + j) ? 1.5f : 0.0f) - 0.5f * v[j];
            } else if (epi == 2) {
                #pragma unroll
                for (int j = 0; j < 4; j++) v[j] *= rs;
            } else if (epi == 3) {
                #pragma unroll
                for (int j = 0; j < 4; j++) {
                    float Lv = Dp[(size_t)r * DD + c0 + j];
                    float g  = Cb[(size_t)r * DD + c0 + j] - v[j];
                    v[j] = sice_f(Lv, g, dec);
                }
            }
            *(float4*)(Dp + (size_t)r * DD + c0) = make_float4(v[0], v[1], v[2], v[3]);
            if (ti != tj) {
                #pragma unroll
                for (int j = 0; j < 4; j++) Dp[(size_t)(c0+j) * DD + r] = v[j];
            }
            if (trp != nullptr && ti == tj) {
                #pragma unroll
                for (int j = 0; j < 4; j++)
                    if (r == c0 + j) dsum += v[j];
            }
        }
    }
    if (trp != nullptr && ti == tj) {
        dred[tid] = dsum;
        __syncthreads();
        if (tid == 0) {
            float s2 = 0.f;
            for (int u = 0; u < 256; u++) s2 += dred[u];
            trp[b * 4 + ti] = s2;
        }
    }
}

// ---------------------------------------------------------------------------
// Split-K fused pair: z<NB -> D1=A1@B1 ; z>=NB -> D2=A2@B2 (symmetric, epi 0)
// grid (10, 1, 2*NB), 256 threads
// ---------------------------------------------------------------------------
__global__ __launch_bounds__(256, 2) void bgemm_pair(
    const float* __restrict__ A1, const float* __restrict__ B1, float* __restrict__ D1,
    const float* __restrict__ A2, const float* __restrict__ B2, float* __restrict__ D2)
{
    const int z = blockIdx.z;
    const int b = z & (NB - 1);
    const bool second = z >= NB;
    const float* Ap = (second ? A2 : A1) + (size_t)b * MAT;
    const float* Bp = (second ? B2 : B1) + (size_t)b * MAT;
    float* Dp = (second ? D2 : D1) + (size_t)b * MAT;

    int ti, tj; tilemap(blockIdx.x, ti, tj);
    const int m0 = ti * 64, n0 = tj * 64;

    __shared__ __align__(16) float S[8704];

    const int tid = threadIdx.x;
    const int half = tid >> 7, lt = tid & 127;
    const int tc = lt & 15, tr8 = lt >> 4;
    const int kb0 = half * 128;

    float* const SA0 = S + (half * 2 + 0) * 1088;
    float* const SA1 = S + (half * 2 + 1) * 1088;
    float* const SB0 = S + 4352 + (half * 2 + 0) * 1088;
    float* const SB1 = S + 4352 + (half * 2 + 1) * 1088;

    float4 pa[2], pb[2];
    float acc[8][4] = {};

    #pragma unroll
    for (int h = 0; h < 2; h++) {
        int fi = lt + 128 * h;
        int row = fi >> 2, q = fi & 3;
        pa[h] = *(const float4*)(Ap + (size_t)(m0 + row) * DD + kb0 + q * 4);
        int kr = fi >> 4, nc = fi & 15;
        pb[h] = *(const float4*)(Bp + (size_t)(kb0 + kr) * DD + n0 + nc * 4);
    }
    #pragma unroll
    for (int h = 0; h < 2; h++) {
        int fi = lt + 128 * h;
        int row = fi >> 2, q = fi & 3;
        SA0[(q*4+0)*68+row] = pa[h].x; SA0[(q*4+1)*68+row] = pa[h].y;
        SA0[(q*4+2)*68+row] = pa[h].z; SA0[(q*4+3)*68+row] = pa[h].w;
        int kr = fi >> 4, nc = fi & 15;
        *(float4*)(SB0 + kr*68 + nc*4) = pb[h];
    }
    __syncthreads();

    const int NCHH = 128 / KC;
    for (int ch = 0; ch < NCHH; ch++) {
        const float* cA = (ch & 1) ? SA1 : SA0;
        const float* cB = (ch & 1) ? SB1 : SB0;
        if (ch + 1 < NCHH) {
            const int k0 = kb0 + (ch + 1) * KC;
            #pragma unroll
            for (int h = 0; h < 2; h++) {
                int fi = lt + 128 * h;
                int row = fi >> 2, q = fi & 3;
                pa[h] = *(const float4*)(Ap + (size_t)(m0 + row) * DD + k0 + q * 4);
                int kr = fi >> 4, nc = fi & 15;
                pb[h] = *(const float4*)(Bp + (size_t)(k0 + kr) * DD + n0 + nc * 4);
            }
        }
        GEMM_COMPUTE_P(cA, cB);
        if (ch + 1 < NCHH) {
            float* nA = (ch & 1) ? SA0 : SA1;
            float* nB = (ch & 1) ? SB0 : SB1;
            #pragma unroll
            for (int h = 0; h < 2; h++) {
                int fi = lt + 128 * h;
                int row = fi >> 2, q = fi & 3;
                nA[(q*4+0)*68+row] = pa[h].x; nA[(q*4+1)*68+row] = pa[h].y;
                nA[(q*4+2)*68+row] = pa[h].z; nA[(q*4+3)*68+row] = pa[h].w;
                int kr = fi >> 4, nc = fi & 15;
                *(float4*)(nB + kr*68 + nc*4) = pb[h];
            }
            __syncthreads();
        }
    }

    __syncthreads();
    if (half == 1) {
        #pragma unroll
        for (int i = 0; i < 8; i++)
            *(float4*)(S + lt * 36 + i * 4) =
                make_float4(acc[i][0], acc[i][1], acc[i][2], acc[i][3]);
    }
    __syncthreads();
    if (half == 0) {
        #pragma unroll
        for (int i = 0; i < 8; i++) {
            float4 o = *(const float4*)(S + lt * 36 + i * 4);
            const int r = m0 + tr8 * 8 + i;
            const int c0 = n0 + tc * 4;
            float v[4] = {acc[i][0] + o.x, acc[i][1] + o.y,
                          acc[i][2] + o.z, acc[i][3] + o.w};
            *(float4*)(Dp + (size_t)r * DD + c0) = make_float4(v[0], v[1], v[2], v[3]);
            if (ti != tj) {
                #pragma unroll
                for (int j = 0; j < 4; j++) Dp[(size_t)(c0+j) * DD + r] = v[j];
            }
        }
    }
}

// ---------------------------------------------------------------------------
// small kernels
// ---------------------------------------------------------------------------
// trace of raw C (for normalization) + jc = sum(1e-10 + 1e-9*jitter)
__global__ void tracek0(const float* __restrict__ X, const float* __restrict__ jitter,
                        float* __restrict__ tr0, float* __restrict__ jcp)
{
    const int b = blockIdx.x;
    const int t = threadIdx.x;
    float v = X[(size_t)b * MAT + t * 257];
    float jt = 1e-10f + 1e-9f * jitter[t];
    __shared__ float sh[8], shj[8];
    const int lane = t & 31, wid = t >> 5;
    v = warpReduce(v); jt = warpReduce(jt);
    if (lane == 0) { sh[wid] = v; shj[wid] = jt; }
    __syncthreads();
    if (wid == 0) {
        v  = (lane < 8) ? sh[lane]  : 0.f;
        jt = (lane < 8) ? shj[lane] : 0.f;
        v = warpReduce(v); jt = warpReduce(jt);
        if (lane == 0) {
            tr0[b] = v;
            if (b == 0) *jcp = jt;
        }
    }
}

__global__ void scalek(float* __restrict__ C, const float* __restrict__ tr0)
{
    const int idx = blockIdx.x * 256 + threadIdx.x;
    C[idx] *= (1.0f / tr0[idx >> 16]);
}

// A = (S + Ij)/t;  ZY0 = 1.5I - 0.5A ; t from trace partials (+jc) or 1+jc
__global__ void prep_ns(const float* __restrict__ Sm, const float* __restrict__ jitter,
                        const float* __restrict__ trp, const float* __restrict__ jcp,
                        float* __restrict__ A, float* __restrict__ ZY,
                        float* __restrict__ tr_now)
{
    const int idx = blockIdx.x * 256 + threadIdx.x;
    const int b = idx >> 16, rc = idx & 65535, r = rc >> 8, c = rc & 255;
    const float jc = *jcp;
    float t;
    if (trp != nullptr)
        t = ((trp[b*4+0] + trp[b*4+1]) + trp[b*4+2]) + trp[b*4+3] + jc;
    else
        t = 1.0f + jc;
    float v = Sm[idx];
    if (r == c) v += 1e-10f + 1e-9f * jitter[r];
    float a = v * (1.0f / t);
    A[idx] = a;
    ZY[idx] = (r == c ? 1.5f : 0.0f) - 0.5f * a;
    if (rc == 0) tr_now[b] = t;
}

__global__ void gather_out(const float* __restrict__ L, const float* __restrict__ trp,
                           float* __restrict__ out)
{
    const int b = blockIdx.y, i = blockIdx.x, j = threadIdx.x;
    if (j < i) return;
    const float t = ((trp[b*4+0] + trp[b*4+1]) + trp[b*4+2]) + trp[b*4+3];
    const float s = rsqrtf(t);
    const int k = i * 256 - (i * (i - 1)) / 2 + (j - i);
    out[(size_t)b * 32896 + k] = L[(size_t)b * MAT + i * 256 + j] * s;
}

// ---------------------------------------------------------------------------
// Host orchestration
// ---------------------------------------------------------------------------
static void run_inv(const float* Sm, const float* jitter, const float* trp_in,
                    float* zz, float* tr_now, const float* jcp,
                    float* A, float* Y, float* Z, float* Y2, float* Z2, float* ZYt)
{
    const dim3 gs(10, 1, NB);
    prep_ns<<<BMAT / 256, 256>>>(Sm, jitter, trp_in, jcp, A, Z, tr_now);  // Z = ZY0
    bgemm_sym<<<gs, 256>>>(A, Z, Y, tr_now, 0, nullptr, 0.f, nullptr);    // Y = A @ ZY0
    float *Yc = Y, *Zc = Z, *Ya = Y2, *Za = Z2;
    for (int it = 0; it < 5; it++) {
        bgemm_sym<<<gs, 256>>>(Zc, Yc, ZYt, tr_now, 1, nullptr, 0.f, nullptr);
        bgemm_pair<<<dim3(10, 1, 2 * NB), 256>>>(Yc, ZYt, Ya, ZYt, Zc, Za);
        float* t1 = Yc; Yc = Ya; Ya = t1;
        float* t2 = Zc; Zc = Za; Za = t2;
    }
    bgemm_sym<<<gs, 256>>>(Zc, Yc, ZYt, tr_now, 1, nullptr, 0.f, nullptr);
    bgemm_sym<<<gs, 256>>>(ZYt, Zc, zz, tr_now, 2, nullptr, 0.f, nullptr); // * t^-0.5
}

extern "C" void kernel_launch(void* const* d_in, const int* in_sizes, int n_in,
                              void* d_out, int out_size)
{
    (void)in_sizes; (void)n_in; (void)out_size;
    const float* x      = (const float*)d_in[0];
    const float* w      = (const float*)d_in[1];
    const float* gamma  = (const float*)d_in[2];
    const float* beta   = (const float*)d_in[3];
    const float* jitter = (const float*)d_in[4];
    float* out = (float*)d_out;

    float *y, *mats, *small;
    cudaGetSymbolAddress((void**)&y, g_y);
    cudaGetSymbolAddress((void**)&mats, g_mats);
    cudaGetSymbolAddress((void**)&small, g_small);

    float* Cn  = mats + 0u * BMAT;
    float* A   = mats + 1u * BMAT;
    float* Y   = mats + 2u * BMAT;
    float* Z   = mats + 3u * BMAT;
    float* Y2  = mats + 4u * BMAT;
    float* Z2  = mats + 5u * BMAT;
    float* ZYt = mats + 6u * BMAT;
    float* zz  = mats + 7u * BMAT;
    float* LLT = mats + 8u * BMAT;

    float* bn_mean = small;
    float* bn_rstd = small + 256;
    float* rowmean = small + 512;
    float* tr0     = small + 8704;
    float* tr_now  = small + 8736;
    float* jcp     = small + 8768;
    float* trp     = small + 8772;

    const dim3 gs(10, 1, NB);

    // Stage 1: conv + BN + ReLU
    conv_gemm<<<dim3(13, 4, NB), 128>>>(x, w, y);
    bn_stats<<<DD, 256>>>(y, bn_mean, bn_rstd);
    bn_apply<<<NB * DD, 256>>>(y, bn_mean, bn_rstd, gamma, beta, rowmean);

    // Stage 2: covariance + trace normalize (Cn == normalized C == sym_C)
    cov_sym<<<gs, 128>>>(y, rowmean, Cn);
    tracek0<<<NB, 256>>>(Cn, jitter, tr0, jcp);
    scalek<<<BMAT / 256, 256>>>(Cn, tr0);

    // Stage 3: LLT = inv_sqrtm(Cn + Ij)^2 ; tr(Cn+Ij) = 1 + jc analytically
    run_inv(Cn, jitter, nullptr, zz, tr_now, jcp, A, Y, Z, Y2, Z2, ZYt);
    bgemm_sym<<<gs, 256>>>(zz, zz, LLT, tr_now, 0, nullptr, 0.f, trp);

    // Stage 4: SICE loop (i=2 has dec==0 -> exact identity, skipped)
    for (int i = 0; i < 2; i++) {
        run_inv(LLT, jitter, trp, zz, tr_now, jcp, A, Y, Z, Y2, Z2, ZYt);
        const float dec = 5.0f * (1.0f - (float)i / 2.0f);
        bgemm_sym<<<gs, 256>>>(zz, zz, LLT, tr_now, 3, Cn, dec, trp);
    }

    // Stage 5: triuvec with trace from final epi3 partials
    gather_out<<<dim3(DD, NB), 256>>>(LLT, trp, out);
}